// round 4
// baseline (speedup 1.0000x reference)
#include <cuda_runtime.h>
#include <cstdint>

#define NB 2
#define NN 50000
#define NF 128
#define NE 500000

// ---------------- scratch ----------------
__device__ int g_cnt[NN];
__device__ int g_off[NN + 1];
__device__ int g_cur[NN];
__device__ int g_elist[NE];

// ---------------- kernel 1: zero counts ----------------
__global__ void k_prep() {
    int i = blockIdx.x * blockDim.x + threadIdx.x;
    if (i < NN) g_cnt[i] = 0;
}

// ---------------- kernel 2: degree histogram ----------------
__global__ void k_hist(const int* __restrict__ dst) {
    int e = blockIdx.x * blockDim.x + threadIdx.x;
    if (e < NE) atomicAdd(&g_cnt[dst[e]], 1);
}

// ---------------- kernel 3: exclusive scan (single block) ----------------
__global__ void k_scan() {
    __shared__ int part[1024];
    int t = threadIdx.x;
    const int CH = (NN + 1023) / 1024;
    int lo = t * CH;
    int hi = lo + CH; if (hi > NN) hi = NN;
    int s = 0;
    for (int i = lo; i < hi; i++) s += g_cnt[i];
    part[t] = s;
    __syncthreads();
    for (int d = 1; d < 1024; d <<= 1) {
        int v = (t >= d) ? part[t - d] : 0;
        __syncthreads();
        part[t] += v;
        __syncthreads();
    }
    int run = (t == 0) ? 0 : part[t - 1];
    for (int i = lo; i < hi; i++) {
        g_off[i] = run;
        g_cur[i] = run;
        run += g_cnt[i];
    }
    if (t == 1023) g_off[NN] = part[1023];
}

// ---------------- kernel 4: CSR fill ----------------
__global__ void k_fill(const int* __restrict__ dst, const int* __restrict__ src) {
    int e = blockIdx.x * blockDim.x + threadIdx.x;
    if (e < NE) {
        int d = dst[e];
        int p = atomicAdd(&g_cur[d], 1);
        g_elist[p] = src[e];
    }
}

// ---------------- kernel 5: fused reduce + tf32 MMA MLP, occupancy 2 ----------------
#define THREADS 256
#define NODES_PER_BLK 32
#define ROWS 64            // 32 nodes * B(2)
#define STRA 260           // A row stride: (r*260+k)%32 == (r*4+k)%32 -> conflict-free
#define STRW 68            // weight chunk row stride (K=64 chunk)
#define STRH 132           // h row stride (K=128)
#define XS_FLOATS (ROWS * STRA)     // 16640
#define WB_FLOATS (128 * STRW)      // 8704
#define SM_FLOATS (XS_FLOATS + WB_FLOATS)   // 25344 floats = 101376 B -> 2 CTAs/SM

__device__ __forceinline__ uint32_t f2tf(float f) {
    uint32_t r;
    asm("cvt.rna.tf32.f32 %0, %1;" : "=r"(r) : "f"(f));
    return r;
}
__device__ __forceinline__ float f2tff(float f) { return __uint_as_float(f2tf(f)); }
__device__ __forceinline__ float4 tf4(float4 v) {
    float4 c;
    c.x = f2tff(v.x); c.y = f2tff(v.y); c.z = f2tff(v.z); c.w = f2tff(v.w);
    return c;
}

__device__ __forceinline__ void mma8(float d[4],
                                     uint32_t a0, uint32_t a1, uint32_t a2, uint32_t a3,
                                     uint32_t b0, uint32_t b1) {
    asm volatile(
        "mma.sync.aligned.m16n8k8.row.col.f32.tf32.tf32.f32 "
        "{%0,%1,%2,%3}, {%4,%5,%6,%7}, {%8,%9}, {%0,%1,%2,%3};\n"
        : "+f"(d[0]), "+f"(d[1]), "+f"(d[2]), "+f"(d[3])
        : "r"(a0), "r"(a1), "r"(a2), "r"(a3), "r"(b0), "r"(b1));
}

__global__ __launch_bounds__(THREADS, 2)
void k_main(const float* __restrict__ x0, const float* __restrict__ w0,
            const float* __restrict__ b0v, const float* __restrict__ w1,
            const float* __restrict__ b1v, float* __restrict__ out) {
    extern __shared__ float sm[];
    float* xs = sm;                 // [64][STRA] A tile (tf32 bits)
    float* wb = sm + XS_FLOATS;     // [128][STRW] weight K-chunk
    float* hs = sm;                 // h tile reuses xs region after GEMM1

    const int t = threadIdx.x;
    const int warp = t >> 5;        // 0..7
    const int lane = t & 31;
    const int gid = lane >> 2;      // 0..7
    const int tig = lane & 3;       // 0..3
    const int node0 = blockIdx.x * NODES_PER_BLK;

    // ======== phase 1: gather + segment mean/max into xs (tf32) ========
    const float NEG_INF = __int_as_float(0xff800000);
    #pragma unroll
    for (int nn = 0; nn < 4; nn++) {
        int ln = warp * 4 + nn;         // local node 0..31
        int n = node0 + ln;
        float4 s0 = make_float4(0.f, 0.f, 0.f, 0.f), s1 = s0;
        float4 m0 = make_float4(NEG_INF, NEG_INF, NEG_INF, NEG_INF), m1 = m0;
        int deg = 0;
        if (n < NN) {
            int beg = g_off[n], end = g_off[n + 1];
            deg = end - beg;
            int ei = beg;
            int ia = 0, ib = 0;
            if (ei < end) ia = g_elist[ei];
            if (ei + 1 < end) ib = g_elist[ei + 1];
            while (ei < end) {
                int pa = (ei + 2 < end) ? g_elist[ei + 2] : 0;
                int pb = (ei + 3 < end) ? g_elist[ei + 3] : 0;
                {
                    float4 v0 = ((const float4*)x0)[ia * 32 + lane];
                    float4 v1 = ((const float4*)x0)[NN * 32 + ia * 32 + lane];
                    s0.x += v0.x; s0.y += v0.y; s0.z += v0.z; s0.w += v0.w;
                    s1.x += v1.x; s1.y += v1.y; s1.z += v1.z; s1.w += v1.w;
                    m0.x = fmaxf(m0.x, v0.x); m0.y = fmaxf(m0.y, v0.y);
                    m0.z = fmaxf(m0.z, v0.z); m0.w = fmaxf(m0.w, v0.w);
                    m1.x = fmaxf(m1.x, v1.x); m1.y = fmaxf(m1.y, v1.y);
                    m1.z = fmaxf(m1.z, v1.z); m1.w = fmaxf(m1.w, v1.w);
                }
                if (ei + 1 < end) {
                    float4 v0 = ((const float4*)x0)[ib * 32 + lane];
                    float4 v1 = ((const float4*)x0)[NN * 32 + ib * 32 + lane];
                    s0.x += v0.x; s0.y += v0.y; s0.z += v0.z; s0.w += v0.w;
                    s1.x += v1.x; s1.y += v1.y; s1.z += v1.z; s1.w += v1.w;
                    m0.x = fmaxf(m0.x, v0.x); m0.y = fmaxf(m0.y, v0.y);
                    m0.z = fmaxf(m0.z, v0.z); m0.w = fmaxf(m0.w, v0.w);
                    m1.x = fmaxf(m1.x, v1.x); m1.y = fmaxf(m1.y, v1.y);
                    m1.z = fmaxf(m1.z, v1.z); m1.w = fmaxf(m1.w, v1.w);
                }
                ia = pa; ib = pb;
                ei += 2;
            }
        }
        float* r0p = xs + (ln * 2 + 0) * STRA;
        float* r1p = xs + (ln * 2 + 1) * STRA;
        float4 mean0, mean1, amax0, amax1;
        if (n < NN && deg > 0) {
            float inv = 1.0f / (float)deg;
            mean0 = make_float4(s0.x * inv, s0.y * inv, s0.z * inv, s0.w * inv);
            mean1 = make_float4(s1.x * inv, s1.y * inv, s1.z * inv, s1.w * inv);
            amax0 = m0; amax1 = m1;
        } else if (n < NN) {
            float4 v0 = ((const float4*)x0)[n * 32 + lane];
            float4 v1 = ((const float4*)x0)[NN * 32 + n * 32 + lane];
            mean0 = v0; amax0 = v0;
            mean1 = v1; amax1 = v1;
        } else {
            float4 z = make_float4(0.f, 0.f, 0.f, 0.f);
            mean0 = z; mean1 = z; amax0 = z; amax1 = z;
        }
        ((float4*)r0p)[lane]         = tf4(mean0);
        ((float4*)(r0p + 128))[lane] = tf4(amax0);
        ((float4*)r1p)[lane]         = tf4(mean1);
        ((float4*)(r1p + 128))[lane] = tf4(amax1);
    }

    // ======== warp tile mapping: 32 rows x 32 cols (8 warps = 2x4 grid) ========
    const int rg = warp >> 2;          // 0..1
    const int cg = warp & 3;           // 0..3
    const int mr = rg * 32;
    const int nc = cg * 32;

    const uint32_t* xsu = (const uint32_t*)xs;
    const uint32_t* wbu = (const uint32_t*)wb;

    // ======== GEMM1: h = relu(x @ w0^T + b0), K=256 in 4 chunks of 64 ========
    float d1[2][4][4];
    #pragma unroll
    for (int j = 0; j < 4; j++) {
        int c0 = nc + 8 * j + 2 * tig;
        float bb0 = b0v[c0], bb1 = b0v[c0 + 1];
        #pragma unroll
        for (int mi = 0; mi < 2; mi++) {
            d1[mi][j][0] = bb0; d1[mi][j][1] = bb1;
            d1[mi][j][2] = bb0; d1[mi][j][3] = bb1;
        }
    }

    #pragma unroll
    for (int kc = 0; kc < 4; kc++) {
        __syncthreads();
        // stage w0 chunk [128 out][64 k] -> wb (tf32-rounded)
        for (int i = t; i < 128 * 16; i += THREADS) {
            int col = i >> 4;
            int q = i & 15;
            float4 v = *(const float4*)(w0 + col * 256 + kc * 64 + q * 4);
            *(float4*)(wb + col * STRW + q * 4) = tf4(v);
        }
        __syncthreads();

        #pragma unroll
        for (int ks = 0; ks < 8; ks++) {
            int kk = kc * 64 + ks * 8;
            int kl = ks * 8;
            uint32_t a[2][4], b[4][2];
            #pragma unroll
            for (int mi = 0; mi < 2; mi++) {
                int r0 = mr + mi * 16 + gid;
                a[mi][0] = xsu[r0 * STRA + kk + tig];
                a[mi][1] = xsu[(r0 + 8) * STRA + kk + tig];
                a[mi][2] = xsu[r0 * STRA + kk + tig + 4];
                a[mi][3] = xsu[(r0 + 8) * STRA + kk + tig + 4];
            }
            #pragma unroll
            for (int j = 0; j < 4; j++) {
                int c = nc + 8 * j + gid;
                b[j][0] = wbu[c * STRW + kl + tig];
                b[j][1] = wbu[c * STRW + kl + tig + 4];
            }
            #pragma unroll
            for (int mi = 0; mi < 2; mi++)
                #pragma unroll
                for (int j = 0; j < 4; j++)
                    mma8(d1[mi][j], a[mi][0], a[mi][1], a[mi][2], a[mi][3],
                         b[j][0], b[j][1]);
        }
    }

    __syncthreads();   // xs and wb fully consumed by all warps

    // store relu(h) as tf32 into hs[row][k] (stride STRH), stage w1 chunk0 -> wb
    #pragma unroll
    for (int mi = 0; mi < 2; mi++) {
        #pragma unroll
        for (int j = 0; j < 4; j++) {
            int r0 = mr + mi * 16 + gid;
            int c0 = nc + 8 * j + 2 * tig;
            hs[r0 * STRH + c0]           = f2tff(fmaxf(d1[mi][j][0], 0.f));
            hs[r0 * STRH + c0 + 1]       = f2tff(fmaxf(d1[mi][j][1], 0.f));
            hs[(r0 + 8) * STRH + c0]     = f2tff(fmaxf(d1[mi][j][2], 0.f));
            hs[(r0 + 8) * STRH + c0 + 1] = f2tff(fmaxf(d1[mi][j][3], 0.f));
        }
    }

    // ======== GEMM2: out = x0 + h @ w1^T + b1, K=128 in 2 chunks of 64 ========
    float d2[2][4][4];
    #pragma unroll
    for (int j = 0; j < 4; j++) {
        int c0 = nc + 8 * j + 2 * tig;
        float bb0 = b1v[c0], bb1 = b1v[c0 + 1];
        #pragma unroll
        for (int mi = 0; mi < 2; mi++) {
            d2[mi][j][0] = bb0; d2[mi][j][1] = bb1;
            d2[mi][j][2] = bb0; d2[mi][j][3] = bb1;
        }
    }
    const uint32_t* hsu = (const uint32_t*)hs;

    #pragma unroll
    for (int kc = 0; kc < 2; kc++) {
        __syncthreads();
        for (int i = t; i < 128 * 16; i += THREADS) {
            int col = i >> 4;
            int q = i & 15;
            float4 v = *(const float4*)(w1 + col * 128 + kc * 64 + q * 4);
            *(float4*)(wb + col * STRW + q * 4) = tf4(v);
        }
        __syncthreads();

        #pragma unroll
        for (int ks = 0; ks < 8; ks++) {
            int kk = kc * 64 + ks * 8;
            int kl = ks * 8;
            uint32_t a[2][4], b[4][2];
            #pragma unroll
            for (int mi = 0; mi < 2; mi++) {
                int r0 = mr + mi * 16 + gid;
                a[mi][0] = hsu[r0 * STRH + kk + tig];
                a[mi][1] = hsu[(r0 + 8) * STRH + kk + tig];
                a[mi][2] = hsu[r0 * STRH + kk + tig + 4];
                a[mi][3] = hsu[(r0 + 8) * STRH + kk + tig + 4];
            }
            #pragma unroll
            for (int j = 0; j < 4; j++) {
                int c = nc + 8 * j + gid;
                b[j][0] = wbu[c * STRW + kl + tig];
                b[j][1] = wbu[c * STRW + kl + tig + 4];
            }
            #pragma unroll
            for (int mi = 0; mi < 2; mi++)
                #pragma unroll
                for (int j = 0; j < 4; j++)
                    mma8(d2[mi][j], a[mi][0], a[mi][1], a[mi][2], a[mi][3],
                         b[j][0], b[j][1]);
        }
    }

    // ======== epilogue: residual + store ========
    #pragma unroll
    for (int mi = 0; mi < 2; mi++) {
        #pragma unroll
        for (int j = 0; j < 4; j++) {
            int c0 = nc + 8 * j + 2 * tig;
            #pragma unroll
            for (int h = 0; h < 2; h++) {
                int r = mr + mi * 16 + gid + h * 8;
                int n = node0 + (r >> 1);
                if (n < NN) {
                    int b = r & 1;
                    int base = b * NN * NF + n * NF + c0;
                    float2 xv = *(const float2*)(x0 + base);
                    float2 o;
                    o.x = xv.x + d2[mi][j][h * 2 + 0];
                    o.y = xv.y + d2[mi][j][h * 2 + 1];
                    *(float2*)(out + base) = o;
                }
            }
        }
    }
}

// ---------------- launcher ----------------
extern "C" void kernel_launch(void* const* d_in, const int* in_sizes, int n_in,
                              void* d_out, int out_size) {
    const float* x0  = (const float*)d_in[0];
    const int*   dst = (const int*)d_in[1];
    const int*   src = (const int*)d_in[2];
    const float* w0  = (const float*)d_in[3];
    const float* b0  = (const float*)d_in[4];
    const float* w1  = (const float*)d_in[5];
    const float* b1  = (const float*)d_in[6];
    float* out = (float*)d_out;

    cudaFuncSetAttribute(k_main, cudaFuncAttributeMaxDynamicSharedMemorySize,
                         SM_FLOATS * (int)sizeof(float));

    k_prep<<<(NN + 255) / 256, 256>>>();
    k_hist<<<(NE + 255) / 256, 256>>>(dst);
    k_scan<<<1, 1024>>>();
    k_fill<<<(NE + 255) / 256, 256>>>(dst, src);

    int tiles = (NN + NODES_PER_BLK - 1) / NODES_PER_BLK;   // 1563
    k_main<<<tiles, THREADS, SM_FLOATS * (int)sizeof(float)>>>(x0, w0, b0, w1, b1, out);
}

// round 6
// speedup vs baseline: 1.3063x; 1.3063x over previous
#include <cuda_runtime.h>
#include <cstdint>

#define NB 2
#define NN 50000
#define NF 128
#define NE 500000

// ---------------- scratch ----------------
__device__ int g_cnt[NN];      // zero-initialized at module load; re-zeroed by k_scan each call
__device__ int g_off[NN + 1];
__device__ int g_cur[NN];
__device__ int g_elist[NE];

// ---------------- kernel 1: degree histogram (g_cnt is pre-zeroed) ----------------
__global__ void k_hist(const int* __restrict__ dst) {
    int e = blockIdx.x * blockDim.x + threadIdx.x;
    if (e < NE) atomicAdd(&g_cnt[dst[e]], 1);
}

// ---------------- kernel 2: exclusive scan (single block) + re-zero g_cnt ----------------
__global__ void k_scan() {
    __shared__ int part[1024];
    int t = threadIdx.x;
    const int CH = (NN + 1023) / 1024;
    int lo = t * CH;
    int hi = lo + CH; if (hi > NN) hi = NN;
    int s = 0;
    for (int i = lo; i < hi; i++) s += g_cnt[i];
    part[t] = s;
    __syncthreads();
    for (int d = 1; d < 1024; d <<= 1) {
        int v = (t >= d) ? part[t - d] : 0;
        __syncthreads();
        part[t] += v;
        __syncthreads();
    }
    int run = (t == 0) ? 0 : part[t - 1];
    for (int i = lo; i < hi; i++) {
        int c = g_cnt[i];
        g_off[i] = run;
        g_cur[i] = run;
        run += c;
        g_cnt[i] = 0;          // restore invariant for the next kernel_launch call
    }
    if (t == 1023) g_off[NN] = part[1023];
}

// ---------------- kernel 3: CSR fill ----------------
__global__ void k_fill(const int* __restrict__ dst, const int* __restrict__ src) {
    int e = blockIdx.x * blockDim.x + threadIdx.x;
    if (e < NE) {
        int d = dst[e];
        int p = atomicAdd(&g_cur[d], 1);
        g_elist[p] = src[e];
    }
}

// ---------------- kernel 4: fused reduce + tf32 MMA MLP ----------------
#define ROWS 128           // 64 nodes * B(2)
#define NODES_PER_BLK 64
#define STRA 260           // A row stride: (r*260+k)%32 == (r*4+k)%32 -> conflict-free
#define STRB 132           // B/h row stride
#define XS_FLOATS (ROWS * STRA)     // 33280
#define WB_FLOATS (128 * STRB)      // 16896
#define SM_FLOATS (XS_FLOATS + WB_FLOATS)   // 50176 floats = 200704 B

__device__ __forceinline__ uint32_t f2tf(float f) {
    uint32_t r;
    asm("cvt.rna.tf32.f32 %0, %1;" : "=r"(r) : "f"(f));
    return r;
}
__device__ __forceinline__ float f2tff(float f) { return __uint_as_float(f2tf(f)); }
__device__ __forceinline__ float4 tf4(float4 v) {
    float4 c;
    c.x = f2tff(v.x); c.y = f2tff(v.y); c.z = f2tff(v.z); c.w = f2tff(v.w);
    return c;
}

__device__ __forceinline__ void mma8(float d[4],
                                     uint32_t a0, uint32_t a1, uint32_t a2, uint32_t a3,
                                     uint32_t b0, uint32_t b1) {
    asm volatile(
        "mma.sync.aligned.m16n8k8.row.col.f32.tf32.tf32.f32 "
        "{%0,%1,%2,%3}, {%4,%5,%6,%7}, {%8,%9}, {%0,%1,%2,%3};\n"
        : "+f"(d[0]), "+f"(d[1]), "+f"(d[2]), "+f"(d[3])
        : "r"(a0), "r"(a1), "r"(a2), "r"(a3), "r"(b0), "r"(b1));
}

__global__ __launch_bounds__(512, 1)
void k_main(const float* __restrict__ x0, const float* __restrict__ w0,
            const float* __restrict__ b0v, const float* __restrict__ w1,
            const float* __restrict__ b1v, float* __restrict__ out) {
    extern __shared__ float sm[];
    float* xs = sm;                 // [128][STRA] A tile (tf32 bits)
    float* wb = sm + XS_FLOATS;     // [128][STRB] weight chunk
    float* hs = sm;                 // h tile reuses xs region after GEMM1

    const int t = threadIdx.x;
    const int warp = t >> 5;
    const int lane = t & 31;
    const int gid = lane >> 2;      // 0..7
    const int tig = lane & 3;       // 0..3
    const int node0 = blockIdx.x * NODES_PER_BLK;

    // ---- stage w0 chunk0 (k 0..127) into wb BEFORE gather (wb idle during gather) ----
    for (int i = t; i < 128 * 32; i += 512) {
        int col = i >> 5;
        int q = i & 31;
        float4 v = ((const float4*)(w0 + col * 256))[q];
        *(float4*)(wb + col * STRB + q * 4) = tf4(v);
    }

    // ======== phase 1: gather + segment mean/max into xs (tf32) ========
    const float NEG_INF = __int_as_float(0xff800000);
    #pragma unroll
    for (int nn = 0; nn < 4; nn++) {
        int ln = warp * 4 + nn;         // local node 0..63
        int n = node0 + ln;
        float4 s0 = make_float4(0.f, 0.f, 0.f, 0.f), s1 = s0;
        float4 m0 = make_float4(NEG_INF, NEG_INF, NEG_INF, NEG_INF), m1 = m0;
        int deg = 0;
        if (n < NN) {
            int beg = g_off[n], end = g_off[n + 1];
            deg = end - beg;
            int ei = beg;
            int ia = 0, ib = 0;
            if (ei < end) ia = g_elist[ei];
            if (ei + 1 < end) ib = g_elist[ei + 1];
            while (ei < end) {
                int pa = (ei + 2 < end) ? g_elist[ei + 2] : 0;
                int pb = (ei + 3 < end) ? g_elist[ei + 3] : 0;
                {
                    float4 v0 = ((const float4*)x0)[ia * 32 + lane];
                    float4 v1 = ((const float4*)x0)[NN * 32 + ia * 32 + lane];
                    s0.x += v0.x; s0.y += v0.y; s0.z += v0.z; s0.w += v0.w;
                    s1.x += v1.x; s1.y += v1.y; s1.z += v1.z; s1.w += v1.w;
                    m0.x = fmaxf(m0.x, v0.x); m0.y = fmaxf(m0.y, v0.y);
                    m0.z = fmaxf(m0.z, v0.z); m0.w = fmaxf(m0.w, v0.w);
                    m1.x = fmaxf(m1.x, v1.x); m1.y = fmaxf(m1.y, v1.y);
                    m1.z = fmaxf(m1.z, v1.z); m1.w = fmaxf(m1.w, v1.w);
                }
                if (ei + 1 < end) {
                    float4 v0 = ((const float4*)x0)[ib * 32 + lane];
                    float4 v1 = ((const float4*)x0)[NN * 32 + ib * 32 + lane];
                    s0.x += v0.x; s0.y += v0.y; s0.z += v0.z; s0.w += v0.w;
                    s1.x += v1.x; s1.y += v1.y; s1.z += v1.z; s1.w += v1.w;
                    m0.x = fmaxf(m0.x, v0.x); m0.y = fmaxf(m0.y, v0.y);
                    m0.z = fmaxf(m0.z, v0.z); m0.w = fmaxf(m0.w, v0.w);
                    m1.x = fmaxf(m1.x, v1.x); m1.y = fmaxf(m1.y, v1.y);
                    m1.z = fmaxf(m1.z, v1.z); m1.w = fmaxf(m1.w, v1.w);
                }
                ia = pa; ib = pb;
                ei += 2;
            }
        }
        float* r0p = xs + (ln * 2 + 0) * STRA;
        float* r1p = xs + (ln * 2 + 1) * STRA;
        float4 mean0, mean1, amax0, amax1;
        if (n < NN && deg > 0) {
            float inv = 1.0f / (float)deg;
            mean0 = make_float4(s0.x * inv, s0.y * inv, s0.z * inv, s0.w * inv);
            mean1 = make_float4(s1.x * inv, s1.y * inv, s1.z * inv, s1.w * inv);
            amax0 = m0; amax1 = m1;
        } else if (n < NN) {
            float4 v0 = ((const float4*)x0)[n * 32 + lane];
            float4 v1 = ((const float4*)x0)[NN * 32 + n * 32 + lane];
            mean0 = v0; amax0 = v0;
            mean1 = v1; amax1 = v1;
        } else {
            float4 z = make_float4(0.f, 0.f, 0.f, 0.f);
            mean0 = z; mean1 = z; amax0 = z; amax1 = z;
        }
        ((float4*)r0p)[lane]         = tf4(mean0);
        ((float4*)(r0p + 128))[lane] = tf4(amax0);
        ((float4*)r1p)[lane]         = tf4(mean1);
        ((float4*)(r1p + 128))[lane] = tf4(amax1);
    }

    // ======== warp tile mapping: 32 rows x 32 cols ========
    const int rg = warp >> 2;          // 0..3
    const int cg = warp & 3;           // 0..3
    const int mr = rg * 32;
    const int nc = cg * 32;

    // ======== GEMM1: h = relu(x @ w0^T + b0), K=256 in 2 chunks ========
    float d1[2][4][4];
    #pragma unroll
    for (int j = 0; j < 4; j++) {
        int c0 = nc + 8 * j + 2 * tig;
        float bb0 = b0v[c0], bb1 = b0v[c0 + 1];
        #pragma unroll
        for (int mi = 0; mi < 2; mi++) {
            d1[mi][j][0] = bb0; d1[mi][j][1] = bb1;
            d1[mi][j][2] = bb0; d1[mi][j][3] = bb1;
        }
    }

    const uint32_t* xsu = (const uint32_t*)xs;
    const uint32_t* wbu = (const uint32_t*)wb;

    #pragma unroll
    for (int kc = 0; kc < 2; kc++) {
        __syncthreads();               // kc=0: xs+wb ready; kc=1: wb chunk1 ready
        #pragma unroll 4
        for (int ks = 0; ks < 16; ks++) {
            int kk = kc * 128 + ks * 8;
            uint32_t a[2][4], b[4][2];
            #pragma unroll
            for (int mi = 0; mi < 2; mi++) {
                int r0 = mr + mi * 16 + gid;
                a[mi][0] = xsu[r0 * STRA + kk + tig];
                a[mi][1] = xsu[(r0 + 8) * STRA + kk + tig];
                a[mi][2] = xsu[r0 * STRA + kk + tig + 4];
                a[mi][3] = xsu[(r0 + 8) * STRA + kk + tig + 4];
            }
            #pragma unroll
            for (int j = 0; j < 4; j++) {
                int c = nc + 8 * j + gid;
                b[j][0] = wbu[c * STRB + ks * 8 + tig];
                b[j][1] = wbu[c * STRB + ks * 8 + tig + 4];
            }
            #pragma unroll
            for (int mi = 0; mi < 2; mi++)
                #pragma unroll
                for (int j = 0; j < 4; j++)
                    mma8(d1[mi][j], a[mi][0], a[mi][1], a[mi][2], a[mi][3],
                         b[j][0], b[j][1]);
        }
        if (kc == 0) {
            __syncthreads();           // all warps done reading wb chunk0
            // stage w0 chunk1 (k 128..255)
            for (int i = t; i < 128 * 32; i += 512) {
                int col = i >> 5;
                int q = i & 31;
                float4 v = ((const float4*)(w0 + col * 256 + 128))[q];
                *(float4*)(wb + col * STRB + q * 4) = tf4(v);
            }
        }
    }

    __syncthreads();   // xs and wb fully consumed

    // store relu(h) as tf32 into hs[row][k] (stride STRB); also stage w1 into wb
    #pragma unroll
    for (int mi = 0; mi < 2; mi++) {
        #pragma unroll
        for (int j = 0; j < 4; j++) {
            int r0 = mr + mi * 16 + gid;
            int c0 = nc + 8 * j + 2 * tig;
            hs[r0 * STRB + c0]           = f2tff(fmaxf(d1[mi][j][0], 0.f));
            hs[r0 * STRB + c0 + 1]       = f2tff(fmaxf(d1[mi][j][1], 0.f));
            hs[(r0 + 8) * STRB + c0]     = f2tff(fmaxf(d1[mi][j][2], 0.f));
            hs[(r0 + 8) * STRB + c0 + 1] = f2tff(fmaxf(d1[mi][j][3], 0.f));
        }
    }
    for (int i = t; i < 128 * 32; i += 512) {
        int col = i >> 5;
        int q = i & 31;
        float4 v = ((const float4*)(w1 + col * 128))[q];
        *(float4*)(wb + col * STRB + q * 4) = tf4(v);
    }
    __syncthreads();

    // ======== GEMM2: out = x0 + h @ w1^T + b1, K=128 ========
    float d2[2][4][4];
    #pragma unroll
    for (int j = 0; j < 4; j++) {
        int c0 = nc + 8 * j + 2 * tig;
        float bb0 = b1v[c0], bb1 = b1v[c0 + 1];
        #pragma unroll
        for (int mi = 0; mi < 2; mi++) {
            d2[mi][j][0] = bb0; d2[mi][j][1] = bb1;
            d2[mi][j][2] = bb0; d2[mi][j][3] = bb1;
        }
    }
    const uint32_t* hsu = (const uint32_t*)hs;

    #pragma unroll 4
    for (int ks = 0; ks < 16; ks++) {
        int kk = ks * 8;
        uint32_t a[2][4], b[4][2];
        #pragma unroll
        for (int mi = 0; mi < 2; mi++) {
            int r0 = mr + mi * 16 + gid;
            a[mi][0] = hsu[r0 * STRB + kk + tig];
            a[mi][1] = hsu[(r0 + 8) * STRB + kk + tig];
            a[mi][2] = hsu[r0 * STRB + kk + tig + 4];
            a[mi][3] = hsu[(r0 + 8) * STRB + kk + tig + 4];
        }
        #pragma unroll
        for (int j = 0; j < 4; j++) {
            int c = nc + 8 * j + gid;
            b[j][0] = wbu[c * STRB + kk + tig];
            b[j][1] = wbu[c * STRB + kk + tig + 4];
        }
        #pragma unroll
        for (int mi = 0; mi < 2; mi++)
            #pragma unroll
            for (int j = 0; j < 4; j++)
                mma8(d2[mi][j], a[mi][0], a[mi][1], a[mi][2], a[mi][3],
                     b[j][0], b[j][1]);
    }

    // ======== epilogue: residual + store ========
    #pragma unroll
    for (int mi = 0; mi < 2; mi++) {
        #pragma unroll
        for (int j = 0; j < 4; j++) {
            int c0 = nc + 8 * j + 2 * tig;
            #pragma unroll
            for (int h = 0; h < 2; h++) {
                int r = mr + mi * 16 + gid + h * 8;
                int n = node0 + (r >> 1);
                if (n < NN) {
                    int b = r & 1;
                    int base = b * NN * NF + n * NF + c0;
                    float2 xv = *(const float2*)(x0 + base);
                    float2 o;
                    o.x = xv.x + d2[mi][j][h * 2 + 0];
                    o.y = xv.y + d2[mi][j][h * 2 + 1];
                    *(float2*)(out + base) = o;
                }
            }
        }
    }
}

// ---------------- launcher ----------------
extern "C" void kernel_launch(void* const* d_in, const int* in_sizes, int n_in,
                              void* d_out, int out_size) {
    const float* x0  = (const float*)d_in[0];
    const int*   dst = (const int*)d_in[1];
    const int*   src = (const int*)d_in[2];
    const float* w0  = (const float*)d_in[3];
    const float* b0  = (const float*)d_in[4];
    const float* w1  = (const float*)d_in[5];
    const float* b1  = (const float*)d_in[6];
    float* out = (float*)d_out;

    cudaFuncSetAttribute(k_main, cudaFuncAttributeMaxDynamicSharedMemorySize,
                         SM_FLOATS * (int)sizeof(float));

    k_hist<<<(NE + 255) / 256, 256>>>(dst);
    k_scan<<<1, 1024>>>();
    k_fill<<<(NE + 255) / 256, 256>>>(dst, src);

    int tiles = (NN + NODES_PER_BLK - 1) / NODES_PER_BLK;   // 782
    k_main<<<tiles, 512, SM_FLOATS * (int)sizeof(float)>>>(x0, w0, b0, w1, b1, out);
}